// round 1
// baseline (speedup 1.0000x reference)
#include <cuda_runtime.h>

#define THREADS 256
#define WARPS 8

typedef unsigned long long u64;

// Shared-memory weight cache. All array sizes are multiples of 16B so every
// row used as ulonglong2/float4 is 16B-aligned (dynamic smem base is aligned).
struct __align__(16) Smem {
  float w2[32][64];    // 8 KB
  float w3[64][64];    // 16 KB
  float ow[64][128];   // 32 KB
  float w1[6][32];
  float b1[32], g1[32], be1[32];
  float b2[64], g2[64], be2[64];
  float b3[64];
  float ob[128], lg[128], lb[128];
  float ctr[WARPS][64];  // per-warp contracted (max over K) scratch
};

__device__ __forceinline__ u64 pack2(float x, float y) {
  u64 r; asm("mov.b64 %0, {%1, %2};" : "=l"(r) : "f"(x), "f"(y)); return r;
}
__device__ __forceinline__ void unpack2(u64 v, float &x, float &y) {
  asm("mov.b64 {%0, %1}, %2;" : "=f"(x), "=f"(y) : "l"(v));
}
// Packed 2xfp32 FMA (Blackwell sm_100+). ptxas never emits this from C++.
__device__ __forceinline__ u64 ffma2(u64 a, u64 b, u64 c) {
  u64 d; asm("fma.rn.f32x2 %0, %1, %2, %3;" : "=l"(d) : "l"(a), "l"(b), "l"(c));
  return d;
}

__device__ __forceinline__ float wsum(float v) {
  #pragma unroll
  for (int o = 16; o > 0; o >>= 1) v += __shfl_xor_sync(0xffffffffu, v, o);
  return v;
}

__device__ __forceinline__ void cpy(float* d, const float* s, int n) {
  for (int i = threadIdx.x; i < n; i += THREADS) d[i] = s[i];
}

extern "C" __global__ void __launch_bounds__(THREADS)
so3conv_kernel(const float* __restrict__ pts, const float* __restrict__ nbr,
               const float* __restrict__ w1, const float* __restrict__ b1,
               const float* __restrict__ g1, const float* __restrict__ be1,
               const float* __restrict__ w2, const float* __restrict__ b2,
               const float* __restrict__ g2, const float* __restrict__ be2,
               const float* __restrict__ w3, const float* __restrict__ b3,
               const float* __restrict__ ow, const float* __restrict__ ob,
               const float* __restrict__ lg, const float* __restrict__ lb,
               float* __restrict__ out)
{
  extern __shared__ float smem_raw[];
  Smem* s = reinterpret_cast<Smem*>(smem_raw);
  cpy(&s->w2[0][0], w2, 32 * 64);
  cpy(&s->w3[0][0], w3, 64 * 64);
  cpy(&s->ow[0][0], ow, 64 * 128);
  cpy(&s->w1[0][0], w1, 6 * 32);
  cpy(s->b1, b1, 32); cpy(s->g1, g1, 32); cpy(s->be1, be1, 32);
  cpy(s->b2, b2, 64); cpy(s->g2, g2, 64); cpy(s->be2, be2, 64);
  cpy(s->b3, b3, 64);
  cpy(s->ob, ob, 128); cpy(s->lg, lg, 128); cpy(s->lb, lb, 128);
  __syncthreads();

  const int warp = threadIdx.x >> 5;
  const int lane = threadIdx.x & 31;
  const int point = blockIdx.x * WARPS + warp;

  // ---- rifeat: lane = neighbor k ----
  const float px = pts[point * 3 + 0];
  const float py = pts[point * 3 + 1];
  const float pz = pts[point * 3 + 2];
  const float* nb = nbr + (size_t)point * 96 + lane * 3;
  const float nx = nb[0], ny = nb[1], nz = nb[2];

  const float mx = wsum(nx) * 0.03125f;
  const float my = wsum(ny) * 0.03125f;
  const float mz = wsum(nz) * 0.03125f;

  const float l1x = mx - nx, l1y = my - ny, l1z = mz - nz;
  const float l2x = nx - px, l2y = ny - py, l2z = nz - pz;
  const float l3x = px - mx, l3y = py - my, l3z = pz - mz;
  const float n1 = sqrtf(l1x * l1x + l1y * l1y + l1z * l1z);
  const float n2 = sqrtf(l2x * l2x + l2y * l2y + l2z * l2z);
  const float n3 = sqrtf(l3x * l3x + l3y * l3y + l3z * l3z);
  const float d12 = l1x * l2x + l1y * l2y + l1z * l2z;
  const float d23 = l2x * l3x + l2y * l3y + l2z * l3z;
  const float d31 = l3x * l1x + l3y * l1y + l3z * l1z;
  float f[6];
  f[0] = n1; f[1] = n2; f[2] = n3;
  f[3] = d12 / (n1 * n2 + 1e-7f);
  f[4] = d23 / (n2 * n3 + 1e-7f);
  f[5] = d31 / (n3 * n1 + 1e-7f);

  // ---- layer 1: [6] @ [6,32] + b1, LN(32) lane-local, relu ----
  float x[32];
  #pragma unroll
  for (int j = 0; j < 32; ++j) x[j] = s->b1[j];
  #pragma unroll
  for (int i = 0; i < 6; ++i) {
    const float a = f[i];
    #pragma unroll
    for (int j = 0; j < 32; ++j) x[j] += a * s->w1[i][j];
  }
  {
    float sm = 0.f;
    #pragma unroll
    for (int j = 0; j < 32; ++j) sm += x[j];
    const float mu = sm * (1.f / 32.f);
    float vs = 0.f;
    #pragma unroll
    for (int j = 0; j < 32; ++j) { const float d = x[j] - mu; vs += d * d; }
    const float inv = rsqrtf(vs * (1.f / 32.f) + 1e-5f);
    #pragma unroll
    for (int j = 0; j < 32; ++j)
      x[j] = fmaxf(0.f, (x[j] - mu) * inv * s->g1[j] + s->be1[j]);
  }

  // ---- layer 2: [32] @ [32,64] + b2 (packed f32x2), LN(64), relu ----
  float h[64];
  {
    u64 acc[32];
    const ulonglong2* bb = reinterpret_cast<const ulonglong2*>(s->b2);
    #pragma unroll
    for (int j = 0; j < 16; ++j) { ulonglong2 t = bb[j]; acc[2*j] = t.x; acc[2*j+1] = t.y; }
    #pragma unroll
    for (int i = 0; i < 32; ++i) {
      const u64 aa = pack2(x[i], x[i]);
      const ulonglong2* wr = reinterpret_cast<const ulonglong2*>(s->w2[i]);
      #pragma unroll
      for (int j = 0; j < 16; ++j) {
        const ulonglong2 w = wr[j];
        acc[2*j]   = ffma2(w.x, aa, acc[2*j]);
        acc[2*j+1] = ffma2(w.y, aa, acc[2*j+1]);
      }
    }
    #pragma unroll
    for (int j = 0; j < 32; ++j) unpack2(acc[j], h[2*j], h[2*j+1]);
  }
  {
    float sm = 0.f;
    #pragma unroll
    for (int j = 0; j < 64; ++j) sm += h[j];
    const float mu = sm * (1.f / 64.f);
    float vs = 0.f;
    #pragma unroll
    for (int j = 0; j < 64; ++j) { const float d = h[j] - mu; vs += d * d; }
    const float inv = rsqrtf(vs * (1.f / 64.f) + 1e-5f);
    #pragma unroll
    for (int j = 0; j < 64; ++j)
      h[j] = fmaxf(0.f, (h[j] - mu) * inv * s->g2[j] + s->be2[j]);
  }

  // ---- layer 3: [64] @ [64,64] + b3 (packed), max over K, two 32-col halves ----
  #pragma unroll
  for (int half = 0; half < 2; ++half) {
    u64 acc[16];
    const ulonglong2* bb = reinterpret_cast<const ulonglong2*>(s->b3 + 32 * half);
    #pragma unroll
    for (int j = 0; j < 8; ++j) { ulonglong2 t = bb[j]; acc[2*j] = t.x; acc[2*j+1] = t.y; }
    #pragma unroll
    for (int i = 0; i < 64; ++i) {
      const u64 aa = pack2(h[i], h[i]);
      const ulonglong2* wr = reinterpret_cast<const ulonglong2*>(&s->w3[i][32 * half]);
      #pragma unroll
      for (int j = 0; j < 8; ++j) {
        const ulonglong2 w = wr[j];
        acc[2*j]   = ffma2(w.x, aa, acc[2*j]);
        acc[2*j+1] = ffma2(w.y, aa, acc[2*j+1]);
      }
    }
    float kv[32];
    #pragma unroll
    for (int j = 0; j < 16; ++j) unpack2(acc[j], kv[2*j], kv[2*j+1]);
    // butterfly max across lanes (lanes = K rows); all lanes end replicated
    #pragma unroll
    for (int off = 16; off > 0; off >>= 1) {
      #pragma unroll
      for (int j = 0; j < 32; ++j)
        kv[j] = fmaxf(kv[j], __shfl_xor_sync(0xffffffffu, kv[j], off));
    }
    // lane j owns element j -> predicated store (no dynamic reg indexing)
    #pragma unroll
    for (int j = 0; j < 32; ++j)
      if (lane == j) s->ctr[warp][32 * half + j] = kv[j];
  }
  __syncwarp();

  // ---- layer 4: contracted[64] @ [64,128] + ob, LN(128) across warp ----
  const float* ctr = s->ctr[warp];
  float4 a = *reinterpret_cast<const float4*>(&s->ob[4 * lane]);
  #pragma unroll
  for (int i = 0; i < 64; ++i) {
    const float c = ctr[i];
    const float4 w = *reinterpret_cast<const float4*>(&s->ow[i][4 * lane]);
    a.x += c * w.x; a.y += c * w.y; a.z += c * w.z; a.w += c * w.w;
  }
  const float sm = wsum(a.x + a.y + a.z + a.w);
  const float mu = sm * (1.f / 128.f);
  const float dx = a.x - mu, dy = a.y - mu, dz = a.z - mu, dw = a.w - mu;
  const float vs = wsum(dx * dx + dy * dy + dz * dz + dw * dw);
  const float inv = rsqrtf(vs * (1.f / 128.f) + 1e-5f);
  const float4 g  = *reinterpret_cast<const float4*>(&s->lg[4 * lane]);
  const float4 bb = *reinterpret_cast<const float4*>(&s->lb[4 * lane]);
  float4 o;
  o.x = dx * inv * g.x + bb.x;
  o.y = dy * inv * g.y + bb.y;
  o.z = dz * inv * g.z + bb.z;
  o.w = dw * inv * g.w + bb.w;
  *reinterpret_cast<float4*>(&out[(size_t)point * 128 + 4 * lane]) = o;
}

extern "C" void kernel_launch(void* const* d_in, const int* in_sizes, int n_in,
                              void* d_out, int out_size) {
  const float* pts = (const float*)d_in[0];
  const float* nbr = (const float*)d_in[1];
  const float* w1  = (const float*)d_in[2];
  const float* b1  = (const float*)d_in[3];
  const float* g1  = (const float*)d_in[4];
  const float* be1 = (const float*)d_in[5];
  const float* w2  = (const float*)d_in[6];
  const float* b2  = (const float*)d_in[7];
  const float* g2  = (const float*)d_in[8];
  const float* be2 = (const float*)d_in[9];
  const float* w3  = (const float*)d_in[10];
  const float* b3  = (const float*)d_in[11];
  const float* ow  = (const float*)d_in[12];
  const float* ob  = (const float*)d_in[13];
  const float* lg  = (const float*)d_in[14];
  const float* lb  = (const float*)d_in[15];

  const int P = in_sizes[1] / 96;          // B*N points (nbr_pts = P*K*3)
  const int grid = P / WARPS;              // 32768/8 = 4096

  cudaFuncSetAttribute(so3conv_kernel,
                       cudaFuncAttributeMaxDynamicSharedMemorySize,
                       (int)sizeof(Smem));
  so3conv_kernel<<<grid, THREADS, sizeof(Smem)>>>(
      pts, nbr, w1, b1, g1, be1, w2, b2, g2, be2, w3, b3,
      ow, ob, lg, lb, (float*)d_out);
}